// round 15
// baseline (speedup 1.0000x reference)
#include <cuda_runtime.h>
#include <cuda_fp16.h>
#include <cstdint>

#define DDIM 128
#define NMAX 100000
#define EMAX 1000000
#define EPS 1e-5f
#define SLOTS 64

// ---------------- scratch (device globals; no runtime allocation) ----------
__device__ __align__(256) __half g_agg16[(size_t)NMAX * DDIM];   // A, then h16
__device__ __align__(256) __half g_feat16[(size_t)NMAX * DDIM];
__device__ __align__(256) __half g_w16[DDIM * DDIM];
__device__ __align__(256) int g_cnt[NMAX];
__device__ __align__(256) int g_ell[(size_t)NMAX * SLOTS];
__device__ __align__(16) float g_colsum[DDIM];
__device__ __align__(16) float g_colsumsq[DDIM];

// ------- K0: zero g_cnt + stats, convert W -> fp16 (small, fast) -----------
__global__ void __launch_bounds__(256) k_pre(const float* __restrict__ W, int N) {
    int stride = gridDim.x * blockDim.x;
    int tid0 = blockIdx.x * blockDim.x + threadIdx.x;
    for (int j = tid0; j < N; j += stride) g_cnt[j] = 0;
    if (tid0 < DDIM) { g_colsum[tid0] = 0.f; g_colsumsq[tid0] = 0.f; }
    if (tid0 < DDIM * DDIM / 4) {
        float4 v = reinterpret_cast<const float4*>(W)[tid0];
        __half2 h0 = __floats2half2_rn(v.x, v.y);
        __half2 h1 = __floats2half2_rn(v.z, v.w);
        uint2 u;
        u.x = *reinterpret_cast<uint32_t*>(&h0);
        u.y = *reinterpret_cast<uint32_t*>(&h1);
        reinterpret_cast<uint2*>(g_w16)[tid0] = u;
    }
}

// ------- K1: merged feat->fp16 conversion (blocks 0..CONV-1) +
//             ELL insert (blocks CONV..GRID-1), concurrent roles ------------
#define WORK_CONV 296
#define WORK_GRID 592
__global__ void __launch_bounds__(256)
k_work(const float* __restrict__ feat, const int* __restrict__ src,
       const int* __restrict__ dst, int E, int nf4) {
    int tid = threadIdx.x;
    if (blockIdx.x < WORK_CONV) {
        int stride = WORK_CONV * 256;
        for (int i = blockIdx.x * 256 + tid; i < nf4; i += stride) {
            float4 v = reinterpret_cast<const float4*>(feat)[i];
            __half2 h0 = __floats2half2_rn(v.x, v.y);
            __half2 h1 = __floats2half2_rn(v.z, v.w);
            uint2 u;
            u.x = *reinterpret_cast<uint32_t*>(&h0);
            u.y = *reinterpret_cast<uint32_t*>(&h1);
            reinterpret_cast<uint2*>(g_feat16)[i] = u;
        }
    } else {
        int stride = (WORK_GRID - WORK_CONV) * 256;
        for (int i = (blockIdx.x - WORK_CONV) * 256 + tid; i < E; i += stride) {
            int d = dst[i];
            int pos = atomicAdd(&g_cnt[d], 1);
            if (pos < SLOTS) g_ell[d * SLOTS + pos] = src[i];
        }
    }
}

// ---------------- K2: gather-mean per node (1 warp / node), fp16 in/out ----
__global__ void __launch_bounds__(256) k_gather(int N) {
    uint32_t node = (blockIdx.x * blockDim.x + threadIdx.x) >> 5;
    uint32_t lane = threadIdx.x & 31;
    if (node >= (uint32_t)N) return;
    int cnt = g_cnt[node];
    int m = cnt < SLOTS ? cnt : SLOTS;
    const int* slots = g_ell + node * SLOTS;
    const uint2* f2p = reinterpret_cast<const uint2*>(g_feat16);
    float4 acc = make_float4(0.f, 0.f, 0.f, 0.f);
    int e = 0;
    for (; e + 4 <= m; e += 4) {
        uint32_t s0 = (uint32_t)slots[e] * 32u + lane;
        uint32_t s1 = (uint32_t)slots[e + 1] * 32u + lane;
        uint32_t s2 = (uint32_t)slots[e + 2] * 32u + lane;
        uint32_t s3 = (uint32_t)slots[e + 3] * 32u + lane;
        uint2 u0 = f2p[s0];
        uint2 u1 = f2p[s1];
        uint2 u2 = f2p[s2];
        uint2 u3 = f2p[s3];
        __half2 p0 = __hadd2(*reinterpret_cast<__half2*>(&u0.x),
                             *reinterpret_cast<__half2*>(&u1.x));
        __half2 p1 = __hadd2(*reinterpret_cast<__half2*>(&u0.y),
                             *reinterpret_cast<__half2*>(&u1.y));
        __half2 q0 = __hadd2(*reinterpret_cast<__half2*>(&u2.x),
                             *reinterpret_cast<__half2*>(&u3.x));
        __half2 q1 = __hadd2(*reinterpret_cast<__half2*>(&u2.y),
                             *reinterpret_cast<__half2*>(&u3.y));
        float2 f0 = __half22float2(p0);
        float2 f1 = __half22float2(p1);
        float2 e0 = __half22float2(q0);
        float2 e1 = __half22float2(q1);
        acc.x += f0.x + e0.x;
        acc.y += f0.y + e0.y;
        acc.z += f1.x + e1.x;
        acc.w += f1.y + e1.y;
    }
    if (e + 2 <= m) {
        uint32_t s0 = (uint32_t)slots[e] * 32u + lane;
        uint32_t s1 = (uint32_t)slots[e + 1] * 32u + lane;
        uint2 u0 = f2p[s0];
        uint2 u1 = f2p[s1];
        __half2 p0 = __hadd2(*reinterpret_cast<__half2*>(&u0.x),
                             *reinterpret_cast<__half2*>(&u1.x));
        __half2 p1 = __hadd2(*reinterpret_cast<__half2*>(&u0.y),
                             *reinterpret_cast<__half2*>(&u1.y));
        float2 f0 = __half22float2(p0);
        float2 f1 = __half22float2(p1);
        acc.x += f0.x; acc.y += f0.y; acc.z += f1.x; acc.w += f1.y;
        e += 2;
    }
    if (e < m) {
        uint32_t s0 = (uint32_t)slots[e] * 32u + lane;
        uint2 u0 = f2p[s0];
        float2 f0 = __half22float2(*reinterpret_cast<__half2*>(&u0.x));
        float2 f1 = __half22float2(*reinterpret_cast<__half2*>(&u0.y));
        acc.x += f0.x; acc.y += f0.y; acc.z += f1.x; acc.w += f1.y;
    }
    float inv = 1.0f / fmaxf((float)cnt, 1.0f);
    __half2 o0 = __floats2half2_rn(acc.x * inv, acc.y * inv);
    __half2 o1 = __floats2half2_rn(acc.z * inv, acc.w * inv);
    uint2 ov;
    ov.x = *reinterpret_cast<uint32_t*>(&o0);
    ov.y = *reinterpret_cast<uint32_t*>(&o1);
    reinterpret_cast<uint2*>(g_agg16)[node * 32u + lane] = ov;
}

// ------- K3: persistent fp16 mma GEMM, M=64 tiles, h out fp16 -------------
#define LDPH 136
#define LDPF 132
#define GEMM_GRID 592
__global__ void __launch_bounds__(128, 4)
k_gemm_mma(const float* __restrict__ b, int N, int ntiles) {
    extern __shared__ __half smemh[];
    __half* sW = smemh;                  // [128][136] = 34816 B (persistent)
    __half* sA = smemh + 128 * LDPH;     // [64][136]  = 17408 B
    float* sHA = reinterpret_cast<float*>(sA);   // 32*132*4 = 16896 B window
    __shared__ float sBias[DDIM];
    __shared__ float sPart[512];

    int tid = threadIdx.x;
    int wid = tid >> 5;
    int lane = tid & 31;
    int g = lane >> 2;
    int tig = lane & 3;
    int wr = wid * 16;
    int kc = tid & 31;        // epilogue col group
    int rb = tid >> 5;        // epilogue row thread

    sBias[tid] = b[tid];

    // stage W once (fp16 straight copy)
    {
        const uint4* w4 = reinterpret_cast<const uint4*>(g_w16);
        #pragma unroll
        for (int it = 0; it < 16; it++) {
            int idx = it * 128 + tid;
            int r = idx >> 4;
            int c = idx & 15;
            uint4 v = w4[r * 16 + c];
            *reinterpret_cast<uint4*>(&sW[r * LDPH + c * 8]) = v;
        }
    }

    uint32_t sW_u32 = (uint32_t)__cvta_generic_to_shared(sW);
    uint32_t sA_u32 = (uint32_t)__cvta_generic_to_shared(sA);
    uint32_t b_lrow = ((lane >> 4) & 1) * 8 + (lane & 7);
    uint32_t b_khalf = ((lane >> 3) & 1) * 8;
    uint32_t b_laneoff = sW_u32 + 2u * (b_lrow * LDPH + b_khalf);
    uint32_t a_row = (uint32_t)wr + ((lane >> 3) & 1) * 8 + (lane & 7);
    uint32_t a_khalf = (lane >> 4) * 8;
    uint32_t a_laneoff = sA_u32 + 2u * (a_row * LDPH + a_khalf);

    float s[4] = {0.f, 0.f, 0.f, 0.f};
    float s2[4] = {0.f, 0.f, 0.f, 0.f};

    for (int tile = blockIdx.x; tile < ntiles; tile += GEMM_GRID) {
        int row0 = tile * 64;
        __syncthreads();   // prev epilogue done / first-iter W staged
        {
            const uint4* a4 = reinterpret_cast<const uint4*>(g_agg16);
            #pragma unroll
            for (int it = 0; it < 8; it++) {
                int idx = it * 128 + tid;
                int r = idx >> 4;
                int c = idx & 15;
                int gr = row0 + r;
                uint4 v = (gr < N) ? a4[(size_t)gr * 16 + c]
                                   : make_uint4(0u, 0u, 0u, 0u);
                *reinterpret_cast<uint4*>(&sA[r * LDPH + c * 8]) = v;
            }
        }
        __syncthreads();

        float acc[16][4];
        #pragma unroll
        for (int nt = 0; nt < 16; nt++)
            #pragma unroll
            for (int c = 0; c < 4; c++) acc[nt][c] = 0.f;

        #pragma unroll
        for (int ks = 0; ks < 8; ks++) {
            int k0 = ks * 16;
            uint32_t ua0, ua1, ua2, ua3;
            asm volatile(
                "ldmatrix.sync.aligned.m8n8.x4.shared.b16 {%0,%1,%2,%3}, [%4];"
                : "=r"(ua0), "=r"(ua1), "=r"(ua2), "=r"(ua3)
                : "r"(a_laneoff + 2u * (uint32_t)k0));
            #pragma unroll
            for (int ntp = 0; ntp < 8; ntp++) {
                uint32_t addr = b_laneoff + 2u * (ntp * 16 * LDPH + k0);
                uint32_t b0r, b1r, b2r, b3r;
                asm volatile(
                    "ldmatrix.sync.aligned.m8n8.x4.shared.b16 {%0,%1,%2,%3}, [%4];"
                    : "=r"(b0r), "=r"(b1r), "=r"(b2r), "=r"(b3r) : "r"(addr));
                int nt0 = ntp * 2;
                asm volatile(
                    "mma.sync.aligned.m16n8k16.row.col.f32.f16.f16.f32 "
                    "{%0,%1,%2,%3}, {%4,%5,%6,%7}, {%8,%9}, {%0,%1,%2,%3};"
                    : "+f"(acc[nt0][0]), "+f"(acc[nt0][1]),
                      "+f"(acc[nt0][2]), "+f"(acc[nt0][3])
                    : "r"(ua0), "r"(ua1), "r"(ua2), "r"(ua3),
                      "r"(b0r), "r"(b1r));
                asm volatile(
                    "mma.sync.aligned.m16n8k16.row.col.f32.f16.f16.f32 "
                    "{%0,%1,%2,%3}, {%4,%5,%6,%7}, {%8,%9}, {%0,%1,%2,%3};"
                    : "+f"(acc[nt0 + 1][0]), "+f"(acc[nt0 + 1][1]),
                      "+f"(acc[nt0 + 1][2]), "+f"(acc[nt0 + 1][3])
                    : "r"(ua0), "r"(ua1), "r"(ua2), "r"(ua3),
                      "r"(b2r), "r"(b3r));
            }
        }
        __syncthreads();   // done reading sA; reuse as sHA windows

        #pragma unroll
        for (int win = 0; win < 2; win++) {
            if ((wid >> 1) == win) {
                int lr = wr - win * 32;   // 0 or 16
                #pragma unroll
                for (int nt = 0; nt < 16; nt++) {
                    int c = nt * 8 + 2 * tig;
                    float b0 = sBias[c], b1 = sBias[c + 1];
                    float2 q0 = make_float2(acc[nt][0] + b0, acc[nt][1] + b1);
                    float2 q1 = make_float2(acc[nt][2] + b0, acc[nt][3] + b1);
                    *reinterpret_cast<float2*>(&sHA[(lr + g) * LDPF + c]) = q0;
                    *reinterpret_cast<float2*>(&sHA[(lr + g + 8) * LDPF + c]) = q1;
                }
            }
            __syncthreads();
            int base = win * 32;
            int vrows = N - row0 - base;
            if (vrows > 32) vrows = 32;
            #pragma unroll
            for (int it = 0; it < 8; it++) {
                int r = rb + it * 4;
                if (r < vrows) {
                    float4 v = *reinterpret_cast<float4*>(&sHA[r * LDPF + kc * 4]);
                    s[0] += v.x; s[1] += v.y; s[2] += v.z; s[3] += v.w;
                    s2[0] += v.x * v.x; s2[1] += v.y * v.y;
                    s2[2] += v.z * v.z; s2[3] += v.w * v.w;
                    __half2 h0 = __floats2half2_rn(v.x, v.y);
                    __half2 h1 = __floats2half2_rn(v.z, v.w);
                    uint2 u;
                    u.x = *reinterpret_cast<uint32_t*>(&h0);
                    u.y = *reinterpret_cast<uint32_t*>(&h1);
                    reinterpret_cast<uint2*>(g_agg16)[
                        (size_t)(row0 + base + r) * 32 + kc] = u;
                }
            }
            __syncthreads();
        }
    }

    // final stats reduction
    #pragma unroll
    for (int j = 0; j < 4; j++) sPart[rb * 128 + kc * 4 + j] = s[j];
    __syncthreads();
    if (tid < 128) {
        float t = sPart[tid] + sPart[128 + tid] + sPart[256 + tid] + sPart[384 + tid];
        atomicAdd(&g_colsum[tid], t);
    }
    __syncthreads();
    #pragma unroll
    for (int j = 0; j < 4; j++) sPart[rb * 128 + kc * 4 + j] = s2[j];
    __syncthreads();
    if (tid < 128) {
        float t = sPart[tid] + sPart[128 + tid] + sPart[256 + tid] + sPart[384 + tid];
        atomicAdd(&g_colsumsq[tid], t);
    }
}

// ---------------- K4: finalize: out = feat + relu(h16*scale + shift) -------
__global__ void __launch_bounds__(256)
k_final(const float* __restrict__ feat, const float* __restrict__ gamma,
        const float* __restrict__ beta, float* __restrict__ out,
        float invN, int nf4) {
    __shared__ float sScale[DDIM];
    __shared__ float sShift[DDIM];
    int tid = threadIdx.x;
    if (tid < DDIM) {
        float mean = g_colsum[tid] * invN;
        float var = g_colsumsq[tid] * invN - mean * mean;
        float rstd = rsqrtf(var + EPS);
        float sc = rstd * gamma[tid];
        sScale[tid] = sc;
        sShift[tid] = beta[tid] - mean * sc;
    }
    __syncthreads();
    int stride = gridDim.x * blockDim.x;
    const uint2* h2 = reinterpret_cast<const uint2*>(g_agg16);
    for (int i = blockIdx.x * blockDim.x + tid; i < nf4; i += stride) {
        int c = (i & 31) << 2;
        uint2 hu = h2[i];
        float2 h0 = __half22float2(*reinterpret_cast<__half2*>(&hu.x));
        float2 h1 = __half22float2(*reinterpret_cast<__half2*>(&hu.y));
        float4 fv = reinterpret_cast<const float4*>(feat)[i];
        float4 o;
        o.x = fmaxf(h0.x * sScale[c + 0] + sShift[c + 0], 0.f) + fv.x;
        o.y = fmaxf(h0.y * sScale[c + 1] + sShift[c + 1], 0.f) + fv.y;
        o.z = fmaxf(h1.x * sScale[c + 2] + sShift[c + 2], 0.f) + fv.z;
        o.w = fmaxf(h1.y * sScale[c + 3] + sShift[c + 3], 0.f) + fv.w;
        reinterpret_cast<float4*>(out)[i] = o;
    }
}

// ---------------- launch ----------------
extern "C" void kernel_launch(void* const* d_in, const int* in_sizes, int n_in,
                              void* d_out, int out_size) {
    const float* feature = (const float*)d_in[0];
    const int*   src     = (const int*)d_in[1];
    const int*   dst     = (const int*)d_in[2];
    const float* W       = (const float*)d_in[3];
    const float* b       = (const float*)d_in[4];
    const float* gamma   = (const float*)d_in[5];
    const float* beta    = (const float*)d_in[6];
    float* out = (float*)d_out;

    int N = in_sizes[0] / DDIM;   // 100000
    int E = in_sizes[1];          // 1000000
    int nf4 = N * (DDIM / 4);

    k_pre<<<392, 256>>>(W, N);
    k_work<<<WORK_GRID, 256>>>(feature, src, dst, E, nf4);

    int gw_blocks = ((N * 32) + 255) / 256;
    k_gather<<<gw_blocks, 256>>>(N);

    size_t smem = (size_t)(128 * LDPH + 64 * LDPH) * sizeof(__half); // 52224 B
    cudaFuncSetAttribute(k_gemm_mma,
                         cudaFuncAttributeMaxDynamicSharedMemorySize,
                         (int)smem);
    int ntiles = (N + 63) / 64;
    k_gemm_mma<<<GEMM_GRID, 128, smem>>>(b, N, ntiles);

    k_final<<<1184, 256>>>(feature, gamma, beta, out, 1.0f / (float)N, nf4);
}

// round 16
// speedup vs baseline: 1.0251x; 1.0251x over previous
#include <cuda_runtime.h>
#include <cuda_fp16.h>
#include <cstdint>

#define DDIM 128
#define NMAX 100000
#define EMAX 1000000
#define EPS 1e-5f
#define SLOTS 64

// ---------------- scratch (device globals; no runtime allocation) ----------
__device__ __align__(256) __half g_agg16[(size_t)NMAX * DDIM];   // A, then h16
__device__ __align__(256) __half g_feat16[(size_t)NMAX * DDIM];
__device__ __align__(256) __half g_w16[DDIM * DDIM];
__device__ __align__(256) int g_cnt[NMAX];
__device__ __align__(256) int g_ell[(size_t)NMAX * SLOTS];
__device__ __align__(16) float g_colsum[DDIM];
__device__ __align__(16) float g_colsumsq[DDIM];

// ------- K0a: zero g_cnt + stats, convert W -> fp16 (main stream) ----------
__global__ void __launch_bounds__(256) k_pre(const float* __restrict__ W, int N) {
    int stride = gridDim.x * blockDim.x;
    int tid0 = blockIdx.x * blockDim.x + threadIdx.x;
    for (int j = tid0; j < N; j += stride) g_cnt[j] = 0;
    if (tid0 < DDIM) { g_colsum[tid0] = 0.f; g_colsumsq[tid0] = 0.f; }
    if (tid0 < DDIM * DDIM / 4) {
        float4 v = reinterpret_cast<const float4*>(W)[tid0];
        __half2 h0 = __floats2half2_rn(v.x, v.y);
        __half2 h1 = __floats2half2_rn(v.z, v.w);
        uint2 u;
        u.x = *reinterpret_cast<uint32_t*>(&h0);
        u.y = *reinterpret_cast<uint32_t*>(&h1);
        reinterpret_cast<uint2*>(g_w16)[tid0] = u;
    }
}

// ------- K0b: feature -> fp16 (forked stream, overlaps k_pre+k_insert) -----
__global__ void __launch_bounds__(256) k_conv(const float* __restrict__ feat,
                                              int nf4) {
    int stride = gridDim.x * blockDim.x;
    for (int i = blockIdx.x * blockDim.x + threadIdx.x; i < nf4; i += stride) {
        float4 v = reinterpret_cast<const float4*>(feat)[i];
        __half2 h0 = __floats2half2_rn(v.x, v.y);
        __half2 h1 = __floats2half2_rn(v.z, v.w);
        uint2 u;
        u.x = *reinterpret_cast<uint32_t*>(&h0);
        u.y = *reinterpret_cast<uint32_t*>(&h1);
        reinterpret_cast<uint2*>(g_feat16)[i] = u;
    }
}

// ---------------- K1: ELL insert ----------------
__global__ void k_insert(const int* __restrict__ src,
                         const int* __restrict__ dst, int E) {
    int i = blockIdx.x * blockDim.x + threadIdx.x;
    if (i >= E) return;
    int d = dst[i];
    int pos = atomicAdd(&g_cnt[d], 1);
    if (pos < SLOTS) g_ell[d * SLOTS + pos] = src[i];
}

// ---------------- K2: gather-mean per node (1 warp / node), fp16 in/out ----
__global__ void __launch_bounds__(256) k_gather(int N) {
    uint32_t node = (blockIdx.x * blockDim.x + threadIdx.x) >> 5;
    uint32_t lane = threadIdx.x & 31;
    if (node >= (uint32_t)N) return;
    int cnt = g_cnt[node];
    int m = cnt < SLOTS ? cnt : SLOTS;
    const int* slots = g_ell + node * SLOTS;
    const uint2* f2p = reinterpret_cast<const uint2*>(g_feat16);
    float4 acc = make_float4(0.f, 0.f, 0.f, 0.f);
    int e = 0;
    for (; e + 4 <= m; e += 4) {
        uint32_t s0 = (uint32_t)slots[e] * 32u + lane;
        uint32_t s1 = (uint32_t)slots[e + 1] * 32u + lane;
        uint32_t s2 = (uint32_t)slots[e + 2] * 32u + lane;
        uint32_t s3 = (uint32_t)slots[e + 3] * 32u + lane;
        uint2 u0 = f2p[s0];
        uint2 u1 = f2p[s1];
        uint2 u2 = f2p[s2];
        uint2 u3 = f2p[s3];
        __half2 p0 = __hadd2(*reinterpret_cast<__half2*>(&u0.x),
                             *reinterpret_cast<__half2*>(&u1.x));
        __half2 p1 = __hadd2(*reinterpret_cast<__half2*>(&u0.y),
                             *reinterpret_cast<__half2*>(&u1.y));
        __half2 q0 = __hadd2(*reinterpret_cast<__half2*>(&u2.x),
                             *reinterpret_cast<__half2*>(&u3.x));
        __half2 q1 = __hadd2(*reinterpret_cast<__half2*>(&u2.y),
                             *reinterpret_cast<__half2*>(&u3.y));
        float2 f0 = __half22float2(p0);
        float2 f1 = __half22float2(p1);
        float2 e0 = __half22float2(q0);
        float2 e1 = __half22float2(q1);
        acc.x += f0.x + e0.x;
        acc.y += f0.y + e0.y;
        acc.z += f1.x + e1.x;
        acc.w += f1.y + e1.y;
    }
    if (e + 2 <= m) {
        uint32_t s0 = (uint32_t)slots[e] * 32u + lane;
        uint32_t s1 = (uint32_t)slots[e + 1] * 32u + lane;
        uint2 u0 = f2p[s0];
        uint2 u1 = f2p[s1];
        __half2 p0 = __hadd2(*reinterpret_cast<__half2*>(&u0.x),
                             *reinterpret_cast<__half2*>(&u1.x));
        __half2 p1 = __hadd2(*reinterpret_cast<__half2*>(&u0.y),
                             *reinterpret_cast<__half2*>(&u1.y));
        float2 f0 = __half22float2(p0);
        float2 f1 = __half22float2(p1);
        acc.x += f0.x; acc.y += f0.y; acc.z += f1.x; acc.w += f1.y;
        e += 2;
    }
    if (e < m) {
        uint32_t s0 = (uint32_t)slots[e] * 32u + lane;
        uint2 u0 = f2p[s0];
        float2 f0 = __half22float2(*reinterpret_cast<__half2*>(&u0.x));
        float2 f1 = __half22float2(*reinterpret_cast<__half2*>(&u0.y));
        acc.x += f0.x; acc.y += f0.y; acc.z += f1.x; acc.w += f1.y;
    }
    float inv = 1.0f / fmaxf((float)cnt, 1.0f);
    __half2 o0 = __floats2half2_rn(acc.x * inv, acc.y * inv);
    __half2 o1 = __floats2half2_rn(acc.z * inv, acc.w * inv);
    uint2 ov;
    ov.x = *reinterpret_cast<uint32_t*>(&o0);
    ov.y = *reinterpret_cast<uint32_t*>(&o1);
    reinterpret_cast<uint2*>(g_agg16)[node * 32u + lane] = ov;
}

// ------- K3: persistent fp16 mma GEMM, M=64 tiles, h out fp16 -------------
#define LDPH 136
#define LDPF 132
#define GEMM_GRID 592
__global__ void __launch_bounds__(128, 4)
k_gemm_mma(const float* __restrict__ b, int N, int ntiles) {
    extern __shared__ __half smemh[];
    __half* sW = smemh;                  // [128][136] = 34816 B (persistent)
    __half* sA = smemh + 128 * LDPH;     // [64][136]  = 17408 B
    float* sHA = reinterpret_cast<float*>(sA);   // 32*132*4 = 16896 B window
    __shared__ float sBias[DDIM];
    __shared__ float sPart[512];

    int tid = threadIdx.x;
    int wid = tid >> 5;
    int lane = tid & 31;
    int g = lane >> 2;
    int tig = lane & 3;
    int wr = wid * 16;
    int kc = tid & 31;
    int rb = tid >> 5;

    sBias[tid] = b[tid];

    {
        const uint4* w4 = reinterpret_cast<const uint4*>(g_w16);
        #pragma unroll
        for (int it = 0; it < 16; it++) {
            int idx = it * 128 + tid;
            int r = idx >> 4;
            int c = idx & 15;
            uint4 v = w4[r * 16 + c];
            *reinterpret_cast<uint4*>(&sW[r * LDPH + c * 8]) = v;
        }
    }

    uint32_t sW_u32 = (uint32_t)__cvta_generic_to_shared(sW);
    uint32_t sA_u32 = (uint32_t)__cvta_generic_to_shared(sA);
    uint32_t b_lrow = ((lane >> 4) & 1) * 8 + (lane & 7);
    uint32_t b_khalf = ((lane >> 3) & 1) * 8;
    uint32_t b_laneoff = sW_u32 + 2u * (b_lrow * LDPH + b_khalf);
    uint32_t a_row = (uint32_t)wr + ((lane >> 3) & 1) * 8 + (lane & 7);
    uint32_t a_khalf = (lane >> 4) * 8;
    uint32_t a_laneoff = sA_u32 + 2u * (a_row * LDPH + a_khalf);

    float s[4] = {0.f, 0.f, 0.f, 0.f};
    float s2[4] = {0.f, 0.f, 0.f, 0.f};

    for (int tile = blockIdx.x; tile < ntiles; tile += GEMM_GRID) {
        int row0 = tile * 64;
        __syncthreads();
        {
            const uint4* a4 = reinterpret_cast<const uint4*>(g_agg16);
            #pragma unroll
            for (int it = 0; it < 8; it++) {
                int idx = it * 128 + tid;
                int r = idx >> 4;
                int c = idx & 15;
                int gr = row0 + r;
                uint4 v = (gr < N) ? a4[(size_t)gr * 16 + c]
                                   : make_uint4(0u, 0u, 0u, 0u);
                *reinterpret_cast<uint4*>(&sA[r * LDPH + c * 8]) = v;
            }
        }
        __syncthreads();

        float acc[16][4];
        #pragma unroll
        for (int nt = 0; nt < 16; nt++)
            #pragma unroll
            for (int c = 0; c < 4; c++) acc[nt][c] = 0.f;

        #pragma unroll
        for (int ks = 0; ks < 8; ks++) {
            int k0 = ks * 16;
            uint32_t ua0, ua1, ua2, ua3;
            asm volatile(
                "ldmatrix.sync.aligned.m8n8.x4.shared.b16 {%0,%1,%2,%3}, [%4];"
                : "=r"(ua0), "=r"(ua1), "=r"(ua2), "=r"(ua3)
                : "r"(a_laneoff + 2u * (uint32_t)k0));
            #pragma unroll
            for (int ntp = 0; ntp < 8; ntp++) {
                uint32_t addr = b_laneoff + 2u * (ntp * 16 * LDPH + k0);
                uint32_t b0r, b1r, b2r, b3r;
                asm volatile(
                    "ldmatrix.sync.aligned.m8n8.x4.shared.b16 {%0,%1,%2,%3}, [%4];"
                    : "=r"(b0r), "=r"(b1r), "=r"(b2r), "=r"(b3r) : "r"(addr));
                int nt0 = ntp * 2;
                asm volatile(
                    "mma.sync.aligned.m16n8k16.row.col.f32.f16.f16.f32 "
                    "{%0,%1,%2,%3}, {%4,%5,%6,%7}, {%8,%9}, {%0,%1,%2,%3};"
                    : "+f"(acc[nt0][0]), "+f"(acc[nt0][1]),
                      "+f"(acc[nt0][2]), "+f"(acc[nt0][3])
                    : "r"(ua0), "r"(ua1), "r"(ua2), "r"(ua3),
                      "r"(b0r), "r"(b1r));
                asm volatile(
                    "mma.sync.aligned.m16n8k16.row.col.f32.f16.f16.f32 "
                    "{%0,%1,%2,%3}, {%4,%5,%6,%7}, {%8,%9}, {%0,%1,%2,%3};"
                    : "+f"(acc[nt0 + 1][0]), "+f"(acc[nt0 + 1][1]),
                      "+f"(acc[nt0 + 1][2]), "+f"(acc[nt0 + 1][3])
                    : "r"(ua0), "r"(ua1), "r"(ua2), "r"(ua3),
                      "r"(b2r), "r"(b3r));
            }
        }
        __syncthreads();

        #pragma unroll
        for (int win = 0; win < 2; win++) {
            if ((wid >> 1) == win) {
                int lr = wr - win * 32;
                #pragma unroll
                for (int nt = 0; nt < 16; nt++) {
                    int c = nt * 8 + 2 * tig;
                    float b0 = sBias[c], b1 = sBias[c + 1];
                    float2 q0 = make_float2(acc[nt][0] + b0, acc[nt][1] + b1);
                    float2 q1 = make_float2(acc[nt][2] + b0, acc[nt][3] + b1);
                    *reinterpret_cast<float2*>(&sHA[(lr + g) * LDPF + c]) = q0;
                    *reinterpret_cast<float2*>(&sHA[(lr + g + 8) * LDPF + c]) = q1;
                }
            }
            __syncthreads();
            int base = win * 32;
            int vrows = N - row0 - base;
            if (vrows > 32) vrows = 32;
            #pragma unroll
            for (int it = 0; it < 8; it++) {
                int r = rb + it * 4;
                if (r < vrows) {
                    float4 v = *reinterpret_cast<float4*>(&sHA[r * LDPF + kc * 4]);
                    s[0] += v.x; s[1] += v.y; s[2] += v.z; s[3] += v.w;
                    s2[0] += v.x * v.x; s2[1] += v.y * v.y;
                    s2[2] += v.z * v.z; s2[3] += v.w * v.w;
                    __half2 h0 = __floats2half2_rn(v.x, v.y);
                    __half2 h1 = __floats2half2_rn(v.z, v.w);
                    uint2 u;
                    u.x = *reinterpret_cast<uint32_t*>(&h0);
                    u.y = *reinterpret_cast<uint32_t*>(&h1);
                    reinterpret_cast<uint2*>(g_agg16)[
                        (size_t)(row0 + base + r) * 32 + kc] = u;
                }
            }
            __syncthreads();
        }
    }

    #pragma unroll
    for (int j = 0; j < 4; j++) sPart[rb * 128 + kc * 4 + j] = s[j];
    __syncthreads();
    if (tid < 128) {
        float t = sPart[tid] + sPart[128 + tid] + sPart[256 + tid] + sPart[384 + tid];
        atomicAdd(&g_colsum[tid], t);
    }
    __syncthreads();
    #pragma unroll
    for (int j = 0; j < 4; j++) sPart[rb * 128 + kc * 4 + j] = s2[j];
    __syncthreads();
    if (tid < 128) {
        float t = sPart[tid] + sPart[128 + tid] + sPart[256 + tid] + sPart[384 + tid];
        atomicAdd(&g_colsumsq[tid], t);
    }
}

// ---------------- K4: finalize: out = feat + relu(h16*scale + shift) -------
__global__ void __launch_bounds__(256)
k_final(const float* __restrict__ feat, const float* __restrict__ gamma,
        const float* __restrict__ beta, float* __restrict__ out,
        float invN, int nf4) {
    __shared__ float sScale[DDIM];
    __shared__ float sShift[DDIM];
    int tid = threadIdx.x;
    if (tid < DDIM) {
        float mean = g_colsum[tid] * invN;
        float var = g_colsumsq[tid] * invN - mean * mean;
        float rstd = rsqrtf(var + EPS);
        float sc = rstd * gamma[tid];
        sScale[tid] = sc;
        sShift[tid] = beta[tid] - mean * sc;
    }
    __syncthreads();
    int stride = gridDim.x * blockDim.x;
    const uint2* h2 = reinterpret_cast<const uint2*>(g_agg16);
    for (int i = blockIdx.x * blockDim.x + tid; i < nf4; i += stride) {
        int c = (i & 31) << 2;
        uint2 hu = h2[i];
        float2 h0 = __half22float2(*reinterpret_cast<__half2*>(&hu.x));
        float2 h1 = __half22float2(*reinterpret_cast<__half2*>(&hu.y));
        float4 fv = reinterpret_cast<const float4*>(feat)[i];
        float4 o;
        o.x = fmaxf(h0.x * sScale[c + 0] + sShift[c + 0], 0.f) + fv.x;
        o.y = fmaxf(h0.y * sScale[c + 1] + sShift[c + 1], 0.f) + fv.y;
        o.z = fmaxf(h1.x * sScale[c + 2] + sShift[c + 2], 0.f) + fv.z;
        o.w = fmaxf(h1.y * sScale[c + 3] + sShift[c + 3], 0.f) + fv.w;
        reinterpret_cast<float4*>(out)[i] = o;
    }
}

// ---------------- launch (forked-stream capture graph) ----------------
extern "C" void kernel_launch(void* const* d_in, const int* in_sizes, int n_in,
                              void* d_out, int out_size) {
    const float* feature = (const float*)d_in[0];
    const int*   src     = (const int*)d_in[1];
    const int*   dst     = (const int*)d_in[2];
    const float* W       = (const float*)d_in[3];
    const float* b       = (const float*)d_in[4];
    const float* gamma   = (const float*)d_in[5];
    const float* beta    = (const float*)d_in[6];
    float* out = (float*)d_out;

    int N = in_sizes[0] / DDIM;   // 100000
    int E = in_sizes[1];          // 1000000
    int nf4 = N * (DDIM / 4);

    static cudaStream_t sB = nullptr;
    static cudaEvent_t evFork = nullptr;
    static cudaEvent_t evJoin = nullptr;
    if (sB == nullptr) {
        cudaStreamCreateWithFlags(&sB, cudaStreamNonBlocking);
        cudaEventCreateWithFlags(&evFork, cudaEventDisableTiming);
        cudaEventCreateWithFlags(&evJoin, cudaEventDisableTiming);
    }

    // fork: feat->fp16 conversion runs concurrently with pre+insert
    cudaEventRecord(evFork, 0);
    cudaStreamWaitEvent(sB, evFork, 0);
    k_conv<<<592, 256, 0, sB>>>(feature, nf4);
    cudaEventRecord(evJoin, sB);

    k_pre<<<392, 256>>>(W, N);
    k_insert<<<(E + 255) / 256, 256>>>(src, dst, E);

    // join before gather (needs both g_feat16 and g_ell/g_cnt)
    cudaStreamWaitEvent(0, evJoin, 0);

    int gw_blocks = ((N * 32) + 255) / 256;
    k_gather<<<gw_blocks, 256>>>(N);

    size_t smem = (size_t)(128 * LDPH + 64 * LDPH) * sizeof(__half); // 52224 B
    cudaFuncSetAttribute(k_gemm_mma,
                         cudaFuncAttributeMaxDynamicSharedMemorySize,
                         (int)smem);
    int ntiles = (N + 63) / 64;
    k_gemm_mma<<<GEMM_GRID, 128, smem>>>(b, N, ntiles);

    k_final<<<1184, 256>>>(feature, gamma, beta, out, 1.0f / (float)N, nf4);
}